// round 7
// baseline (speedup 1.0000x reference)
#include <cuda_runtime.h>
#include <math.h>

// ---------------- static configuration ----------------
#define BATCH   4
#define A_TOTAL 159882
#define NLEV    5
#define K_ALL   4507
#define POST_N  1000
#define IMG_WF  800.0f
#define IMG_HF  800.0f
#define MIN_SZ  0.001f
#define NMS_T   0.7f
#define BBOX_CLIP 4.135166556742356f

__constant__ int c_n[NLEV]    = {120000, 30000, 7500, 1875, 507};
__constant__ int c_off[NLEV]  = {0, 120000, 150000, 157500, 159375};
__constant__ int c_k[NLEV]    = {1000, 1000, 1000, 1000, 507};
__constant__ int c_soff[NLEV] = {0, 1000, 2000, 3000, 4000};

// ---------------- scratch (device globals; no allocation) ----------------
__device__ int      g_selidx[BATCH * K_ALL];
__device__ float4   g_boxv  [BATCH * K_ALL];   // clipped boxes
__device__ float    g_scorev[BATCH * K_ALL];   // sigmoid scores
__device__ unsigned g_keyv  [BATCH * K_ALL];   // mono(objectness) if valid else 0
__device__ int      g_keepv [BATCH * K_ALL];
__device__ int      g_maxc  [BATCH];           // float bits (coords >= 0)

__device__ __forceinline__ unsigned mono_bits(float f) {
    unsigned u = __float_as_uint(f);
    return (u & 0x80000000u) ? ~u : (u | 0x80000000u);
}

// in-shared-memory bitonic sort, descending, m = power of 2
__device__ __forceinline__ void bitonic_desc(unsigned long long* keys, int m, int t, int NT) {
    for (int k = 2; k <= m; k <<= 1) {
        for (int j = k >> 1; j > 0; j >>= 1) {
            for (int i = t; i < m; i += NT) {
                int ix = i ^ j;
                if (ix > i) {
                    unsigned long long a = keys[i], b = keys[ix];
                    bool desc = ((i & k) == 0);
                    if (desc ? (a < b) : (a > b)) { keys[i] = b; keys[ix] = a; }
                }
            }
            __syncthreads();
        }
    }
}

// ================= Kernel 1: per-(image,level) exact top-k =================
// One block per (image, level). Histogram on 12-bit prefix of monotone float
// key -> threshold bucket -> compact superset -> bitonic sort -> take k.
extern __shared__ unsigned long long sm_u64[];

__global__ void __launch_bounds__(1024, 1)
topk_kernel(const float* __restrict__ obj, int* __restrict__ selidx) {
    const int blk = blockIdx.x;            // 0..19
    const int img = blk / NLEV;
    const int lev = blk % NLEV;
    const int n = c_n[lev], lvoff = c_off[lev], k = c_k[lev], soff = c_soff[lev];
    const float* __restrict__ src = obj + img * A_TOTAL + lvoff;

    unsigned* hist = (unsigned*)sm_u64;    // first 16KB aliased, consumed before reuse
    __shared__ int tsum[1024];
    __shared__ int sh_B, sh_cnt;

    const int t = threadIdx.x, NT = blockDim.x;
    if (t == 0 && lev == 0) g_maxc[img] = 0;   // reset for this replay

    for (int b = t; b < 4096; b += NT) hist[b] = 0u;
    __syncthreads();

    for (int j = t; j < n; j += NT) {
        unsigned u = mono_bits(src[j]);
        atomicAdd(&hist[u >> 20], 1u);
    }
    __syncthreads();

    {
        int base = t * 4;
        tsum[t] = (int)(hist[base] + hist[base + 1] + hist[base + 2] + hist[base + 3]);
    }
    __syncthreads();

    if (t == 0) {
        int cum = 0, B = 0;
        for (int seg = 1023; seg >= 0; seg--) {
            if (cum + tsum[seg] >= k) {
                for (int b = seg * 4 + 3;; b--) {
                    if (cum + (int)hist[b] >= k) { B = b; break; }
                    cum += (int)hist[b];
                }
                break;
            }
            cum += tsum[seg];
        }
        sh_B = B;
        sh_cnt = 0;
    }
    __syncthreads();

    const int B = sh_B;
    for (int j = t; j < n; j += NT) {
        unsigned u = mono_bits(src[j]);
        if ((int)(u >> 20) >= B) {
            int p = atomicAdd(&sh_cnt, 1);
            if (p < 8192)
                sm_u64[p] = ((unsigned long long)u << 32) | (unsigned)(~(unsigned)j);
        }
    }
    __syncthreads();

    int cnt = sh_cnt;
    if (cnt > 8192) cnt = 8192;
    int m = 1;
    while (m < cnt || m < k) m <<= 1;
    if (m > 8192) m = 8192;
    for (int i = cnt + t; i < m; i += NT) sm_u64[i] = 0ULL;
    __syncthreads();

    bitonic_desc(sm_u64, m, t, NT);

    for (int s = t; s < k; s += NT) {
        int j = (int)(~(unsigned)sm_u64[s]);   // local index (ties: asc index, = lax.top_k)
        selidx[img * K_ALL + soff + s] = lvoff + j;
    }
}

// ================= Kernel 2: gather + decode + clip + valid + max_coord =====
__global__ void decode_kernel(const float* __restrict__ obj,
                              const float4* __restrict__ deltas,
                              const float4* __restrict__ anchors) {
    int g = blockIdx.x * blockDim.x + threadIdx.x;
    if (g >= BATCH * K_ALL) return;
    int img = g / K_ALL;
    int idx = g_selidx[g];

    float  o = obj[img * A_TOTAL + idx];
    float4 d = deltas[img * A_TOTAL + idx];
    float4 a = anchors[idx];

    // BoxCoder.decode, no FMA contraction (matches XLA elementwise lowering)
    float wa  = __fsub_rn(a.z, a.x);
    float ha  = __fsub_rn(a.w, a.y);
    float cxa = __fadd_rn(a.x, __fmul_rn(0.5f, wa));
    float cya = __fadd_rn(a.y, __fmul_rn(0.5f, ha));
    float dw  = fminf(d.z, BBOX_CLIP);
    float dh  = fminf(d.w, BBOX_CLIP);
    float cx  = __fadd_rn(__fmul_rn(d.x, wa), cxa);
    float cy  = __fadd_rn(__fmul_rn(d.y, ha), cya);
    float w   = __fmul_rn(expf(dw), wa);
    float h   = __fmul_rn(expf(dh), ha);
    float x1  = __fsub_rn(cx, __fmul_rn(0.5f, w));
    float y1  = __fsub_rn(cy, __fmul_rn(0.5f, h));
    float x2  = __fadd_rn(cx, __fmul_rn(0.5f, w));
    float y2  = __fadd_rn(cy, __fmul_rn(0.5f, h));

    // clip_boxes_to_image
    float x1c = fminf(fmaxf(x1, 0.0f), IMG_WF);
    float y1c = fminf(fmaxf(y1, 0.0f), IMG_HF);
    float x2c = fminf(fmaxf(x2, 0.0f), IMG_WF);
    float y2c = fminf(fmaxf(y2, 0.0f), IMG_HF);

    float score = 1.0f / (1.0f + expf(-o));
    bool valid = (__fsub_rn(x2c, x1c) >= MIN_SZ) &&
                 (__fsub_rn(y2c, y1c) >= MIN_SZ) &&
                 (score >= 0.0f);

    g_boxv[g]   = make_float4(x1c, y1c, x2c, y2c);
    g_scorev[g] = score;
    g_keyv[g]   = valid ? mono_bits(o) : 0u;   // mono(finite) > 0 always

    float mx = fmaxf(fmaxf(x1c, y1c), fmaxf(x2c, y2c));
    atomicMax(&g_maxc[img], __float_as_int(mx));
}

// ================= Kernel 3: per-(image,level) greedy NMS ===================
// Candidates are already in score-descending order (top-k order). Offsets
// reproduce the reference's translated-box IoU arithmetic bit-for-bit.
__global__ void __launch_bounds__(1024, 1)
nms_kernel() {
    const int blk = blockIdx.x;
    const int img = blk / NLEV;
    const int lev = blk % NLEV;
    const int k = c_k[lev], soff = c_soff[lev];
    const int base = img * K_ALL + soff;

    __shared__ float sx1[1024], sy1[1024], sx2[1024], sy2[1024], sarea[1024];
    __shared__ int   skeep[1024];

    const int t = threadIdx.x;
    float maxc = __int_as_float(g_maxc[img]);
    float off  = __fmul_rn((float)lev, __fadd_rn(maxc, 1.0f));

    bool  kv = false;
    float x1 = 0.f, y1 = 0.f, x2 = 0.f, y2 = 0.f, area = 0.f;
    if (t < k) {
        float4 b = g_boxv[base + t];
        x1 = __fadd_rn(b.x, off);
        y1 = __fadd_rn(b.y, off);
        x2 = __fadd_rn(b.z, off);
        y2 = __fadd_rn(b.w, off);
        area = __fmul_rn(__fsub_rn(x2, x1), __fsub_rn(y2, y1));
        kv = (g_keyv[base + t] != 0u);
        sx1[t] = x1; sy1[t] = y1; sx2[t] = x2; sy2[t] = y2; sarea[t] = area;
        skeep[t] = kv ? 1 : 0;
    }
    __syncthreads();

    for (int i = 0; i < k - 1; i++) {
        if (skeep[i] && t > i && kv) {
            float lx = fmaxf(sx1[i], x1), ly = fmaxf(sy1[i], y1);
            float rx = fminf(sx2[i], x2), ry = fminf(sy2[i], y2);
            float ww = fmaxf(__fsub_rn(rx, lx), 0.0f);
            float hh = fmaxf(__fsub_rn(ry, ly), 0.0f);
            float inter = __fmul_rn(ww, hh);
            float denom = __fsub_rn(__fadd_rn(sarea[i], area), inter);
            float iou = __fdiv_rn(inter, denom);
            if (iou > NMS_T) { kv = false; skeep[t] = 0; }
        }
        __syncthreads();
    }

    if (t < k) g_keepv[base + t] = kv ? 1 : 0;
}

// ================= Kernel 4: per-image final sort + emit ====================
__global__ void __launch_bounds__(1024, 1)
final_kernel(float* __restrict__ out) {
    const int img = blockIdx.x;
    const int t = threadIdx.x, NT = blockDim.x;
    const int base = img * K_ALL;
    const int M = 8192;

    for (int s = t; s < M; s += NT) {
        unsigned long long key = 0ULL;
        if (s < K_ALL && g_keepv[base + s]) {
            key = ((unsigned long long)g_keyv[base + s] << 32) | (unsigned)(~(unsigned)s);
        }
        sm_u64[s] = key;
    }
    __syncthreads();

    bitonic_desc(sm_u64, M, t, NT);

    for (int s = t; s < POST_N; s += NT) {
        unsigned long long key = sm_u64[s];
        float4 b = make_float4(0.f, 0.f, 0.f, 0.f);
        float sc = 0.f;
        if ((key >> 32) != 0ULL) {
            int slot = (int)(~(unsigned)key);
            b  = g_boxv[base + slot];
            sc = g_scorev[base + slot];
        }
        float* ob = out + (size_t)(img * POST_N + s) * 4;
        ob[0] = b.x; ob[1] = b.y; ob[2] = b.z; ob[3] = b.w;
        out[BATCH * POST_N * 4 + img * POST_N + s] = sc;
    }
}

// ================= launch ====================
extern "C" void kernel_launch(void* const* d_in, const int* in_sizes, int n_in,
                              void* d_out, int out_size) {
    const float*  obj     = (const float*) d_in[0];   // [4, 159882]
    const float4* deltas  = (const float4*)d_in[1];   // [4, 159882, 4]
    const float4* anchors = (const float4*)d_in[2];   // [159882, 4]
    float* out = (float*)d_out;                       // boxes[4,1000,4] ++ scores[4,1000]

    cudaFuncSetAttribute(topk_kernel,  cudaFuncAttributeMaxDynamicSharedMemorySize, 65536);
    cudaFuncSetAttribute(final_kernel, cudaFuncAttributeMaxDynamicSharedMemorySize, 65536);

    int* selidx;
    cudaGetSymbolAddress((void**)&selidx, g_selidx);

    topk_kernel<<<BATCH * NLEV, 1024, 65536>>>(obj, selidx);
    decode_kernel<<<(BATCH * K_ALL + 255) / 256, 256>>>(obj, deltas, anchors);
    nms_kernel<<<BATCH * NLEV, 1024>>>();
    final_kernel<<<BATCH, 1024, 65536>>>(out);
}

// round 8
// speedup vs baseline: 1.0014x; 1.0014x over previous
#include <cuda_runtime.h>
#include <math.h>

// ---------------- static configuration ----------------
#define BATCH   4
#define A_TOTAL 159882
#define NLEV    5
#define K_ALL   4507
#define POST_N  1000
#define IMG_WF  800.0f
#define IMG_HF  800.0f
#define MIN_SZ  0.001f
#define NMS_T   0.7f
#define BBOX_CLIP 4.135166556742356f

__constant__ int c_n[NLEV]    = {120000, 30000, 7500, 1875, 507};
__constant__ int c_off[NLEV]  = {0, 120000, 150000, 157500, 159375};
__constant__ int c_k[NLEV]    = {1000, 1000, 1000, 1000, 507};
__constant__ int c_soff[NLEV] = {0, 1000, 2000, 3000, 4000};

// ---------------- scratch (device globals; no allocation) ----------------
__device__ int      g_selidx[BATCH * K_ALL];
__device__ float4   g_boxv  [BATCH * K_ALL];   // clipped boxes
__device__ float    g_scorev[BATCH * K_ALL];   // sigmoid scores
__device__ unsigned g_keyv  [BATCH * K_ALL];   // mono(objectness) if valid else 0
__device__ int      g_keepv [BATCH * K_ALL];
__device__ int      g_maxc  [BATCH];           // float bits (coords >= 0)

__device__ __forceinline__ unsigned mono_bits(float f) {
    unsigned u = __float_as_uint(f);
    return (u & 0x80000000u) ? ~u : (u | 0x80000000u);
}

// in-shared-memory bitonic sort, descending, m = power of 2
__device__ __forceinline__ void bitonic_desc(unsigned long long* keys, int m, int t, int NT) {
    for (int k = 2; k <= m; k <<= 1) {
        for (int j = k >> 1; j > 0; j >>= 1) {
            for (int i = t; i < m; i += NT) {
                int ix = i ^ j;
                if (ix > i) {
                    unsigned long long a = keys[i], b = keys[ix];
                    bool desc = ((i & k) == 0);
                    if (desc ? (a < b) : (a > b)) { keys[i] = b; keys[ix] = a; }
                }
            }
            __syncthreads();
        }
    }
}

// ================= Kernel 1: per-(image,level) exact top-k =================
// One block per (image, level). Histogram on 12-bit prefix of monotone float
// key -> threshold bucket -> compact superset -> bitonic sort -> take k.
extern __shared__ unsigned long long sm_u64[];

__global__ void __launch_bounds__(1024, 1)
topk_kernel(const float* __restrict__ obj, int* __restrict__ selidx) {
    const int blk = blockIdx.x;            // 0..19
    const int img = blk / NLEV;
    const int lev = blk % NLEV;
    const int n = c_n[lev], lvoff = c_off[lev], k = c_k[lev], soff = c_soff[lev];
    const float* __restrict__ src = obj + img * A_TOTAL + lvoff;

    unsigned* hist = (unsigned*)sm_u64;    // first 16KB aliased, consumed before reuse
    __shared__ int tsum[1024];
    __shared__ int sh_B, sh_cnt;

    const int t = threadIdx.x, NT = blockDim.x;
    if (t == 0 && lev == 0) g_maxc[img] = 0;   // reset for this replay

    for (int b = t; b < 4096; b += NT) hist[b] = 0u;
    __syncthreads();

    for (int j = t; j < n; j += NT) {
        unsigned u = mono_bits(src[j]);
        atomicAdd(&hist[u >> 20], 1u);
    }
    __syncthreads();

    {
        int base = t * 4;
        tsum[t] = (int)(hist[base] + hist[base + 1] + hist[base + 2] + hist[base + 3]);
    }
    __syncthreads();

    if (t == 0) {
        int cum = 0, B = 0;
        for (int seg = 1023; seg >= 0; seg--) {
            if (cum + tsum[seg] >= k) {
                for (int b = seg * 4 + 3;; b--) {
                    if (cum + (int)hist[b] >= k) { B = b; break; }
                    cum += (int)hist[b];
                }
                break;
            }
            cum += tsum[seg];
        }
        sh_B = B;
        sh_cnt = 0;
    }
    __syncthreads();

    const int B = sh_B;
    for (int j = t; j < n; j += NT) {
        unsigned u = mono_bits(src[j]);
        if ((int)(u >> 20) >= B) {
            int p = atomicAdd(&sh_cnt, 1);
            if (p < 8192)
                sm_u64[p] = ((unsigned long long)u << 32) | (unsigned)(~(unsigned)j);
        }
    }
    __syncthreads();

    int cnt = sh_cnt;
    if (cnt > 8192) cnt = 8192;
    int m = 1;
    while (m < cnt || m < k) m <<= 1;
    if (m > 8192) m = 8192;
    for (int i = cnt + t; i < m; i += NT) sm_u64[i] = 0ULL;
    __syncthreads();

    bitonic_desc(sm_u64, m, t, NT);

    for (int s = t; s < k; s += NT) {
        int j = (int)(~(unsigned)sm_u64[s]);   // local index (ties: asc index, = lax.top_k)
        selidx[img * K_ALL + soff + s] = lvoff + j;
    }
}

// ================= Kernel 2: gather + decode + clip + valid + max_coord =====
__global__ void decode_kernel(const float* __restrict__ obj,
                              const float4* __restrict__ deltas,
                              const float4* __restrict__ anchors) {
    int g = blockIdx.x * blockDim.x + threadIdx.x;
    if (g >= BATCH * K_ALL) return;
    int img = g / K_ALL;
    int idx = g_selidx[g];

    float  o = obj[img * A_TOTAL + idx];
    float4 d = deltas[img * A_TOTAL + idx];
    float4 a = anchors[idx];

    // BoxCoder.decode, no FMA contraction (matches XLA elementwise lowering)
    float wa  = __fsub_rn(a.z, a.x);
    float ha  = __fsub_rn(a.w, a.y);
    float cxa = __fadd_rn(a.x, __fmul_rn(0.5f, wa));
    float cya = __fadd_rn(a.y, __fmul_rn(0.5f, ha));
    float dw  = fminf(d.z, BBOX_CLIP);
    float dh  = fminf(d.w, BBOX_CLIP);
    float cx  = __fadd_rn(__fmul_rn(d.x, wa), cxa);
    float cy  = __fadd_rn(__fmul_rn(d.y, ha), cya);
    float w   = __fmul_rn(expf(dw), wa);
    float h   = __fmul_rn(expf(dh), ha);
    float x1  = __fsub_rn(cx, __fmul_rn(0.5f, w));
    float y1  = __fsub_rn(cy, __fmul_rn(0.5f, h));
    float x2  = __fadd_rn(cx, __fmul_rn(0.5f, w));
    float y2  = __fadd_rn(cy, __fmul_rn(0.5f, h));

    // clip_boxes_to_image
    float x1c = fminf(fmaxf(x1, 0.0f), IMG_WF);
    float y1c = fminf(fmaxf(y1, 0.0f), IMG_HF);
    float x2c = fminf(fmaxf(x2, 0.0f), IMG_WF);
    float y2c = fminf(fmaxf(y2, 0.0f), IMG_HF);

    float score = 1.0f / (1.0f + expf(-o));
    bool valid = (__fsub_rn(x2c, x1c) >= MIN_SZ) &&
                 (__fsub_rn(y2c, y1c) >= MIN_SZ) &&
                 (score >= 0.0f);

    g_boxv[g]   = make_float4(x1c, y1c, x2c, y2c);
    g_scorev[g] = score;
    g_keyv[g]   = valid ? mono_bits(o) : 0u;   // mono(finite) > 0 always

    float mx = fmaxf(fmaxf(x1c, y1c), fmaxf(x2c, y2c));
    atomicMax(&g_maxc[img], __float_as_int(mx));
}

// ================= Kernel 3: per-(image,level) greedy NMS ===================
// Candidates are already in score-descending order (top-k order). Offsets
// reproduce the reference's translated-box IoU arithmetic bit-for-bit.
__global__ void __launch_bounds__(1024, 1)
nms_kernel() {
    const int blk = blockIdx.x;
    const int img = blk / NLEV;
    const int lev = blk % NLEV;
    const int k = c_k[lev], soff = c_soff[lev];
    const int base = img * K_ALL + soff;

    __shared__ float sx1[1024], sy1[1024], sx2[1024], sy2[1024], sarea[1024];
    __shared__ int   skeep[1024];

    const int t = threadIdx.x;
    float maxc = __int_as_float(g_maxc[img]);
    float off  = __fmul_rn((float)lev, __fadd_rn(maxc, 1.0f));

    bool  kv = false;
    float x1 = 0.f, y1 = 0.f, x2 = 0.f, y2 = 0.f, area = 0.f;
    if (t < k) {
        float4 b = g_boxv[base + t];
        x1 = __fadd_rn(b.x, off);
        y1 = __fadd_rn(b.y, off);
        x2 = __fadd_rn(b.z, off);
        y2 = __fadd_rn(b.w, off);
        area = __fmul_rn(__fsub_rn(x2, x1), __fsub_rn(y2, y1));
        kv = (g_keyv[base + t] != 0u);
        sx1[t] = x1; sy1[t] = y1; sx2[t] = x2; sy2[t] = y2; sarea[t] = area;
        skeep[t] = kv ? 1 : 0;
    }
    __syncthreads();

    for (int i = 0; i < k - 1; i++) {
        if (skeep[i] && t > i && kv) {
            float lx = fmaxf(sx1[i], x1), ly = fmaxf(sy1[i], y1);
            float rx = fminf(sx2[i], x2), ry = fminf(sy2[i], y2);
            float ww = fmaxf(__fsub_rn(rx, lx), 0.0f);
            float hh = fmaxf(__fsub_rn(ry, ly), 0.0f);
            float inter = __fmul_rn(ww, hh);
            float denom = __fsub_rn(__fadd_rn(sarea[i], area), inter);
            float iou = __fdiv_rn(inter, denom);
            if (iou > NMS_T) { kv = false; skeep[t] = 0; }
        }
        __syncthreads();
    }

    if (t < k) g_keepv[base + t] = kv ? 1 : 0;
}

// ================= Kernel 4: per-image final sort + emit ====================
__global__ void __launch_bounds__(1024, 1)
final_kernel(float* __restrict__ out) {
    const int img = blockIdx.x;
    const int t = threadIdx.x, NT = blockDim.x;
    const int base = img * K_ALL;
    const int M = 8192;

    for (int s = t; s < M; s += NT) {
        unsigned long long key = 0ULL;
        if (s < K_ALL && g_keepv[base + s]) {
            key = ((unsigned long long)g_keyv[base + s] << 32) | (unsigned)(~(unsigned)s);
        }
        sm_u64[s] = key;
    }
    __syncthreads();

    bitonic_desc(sm_u64, M, t, NT);

    for (int s = t; s < POST_N; s += NT) {
        unsigned long long key = sm_u64[s];
        float4 b = make_float4(0.f, 0.f, 0.f, 0.f);
        float sc = 0.f;
        if ((key >> 32) != 0ULL) {
            int slot = (int)(~(unsigned)key);
            b  = g_boxv[base + slot];
            sc = g_scorev[base + slot];
        }
        float* ob = out + (size_t)(img * POST_N + s) * 4;
        ob[0] = b.x; ob[1] = b.y; ob[2] = b.z; ob[3] = b.w;
        out[BATCH * POST_N * 4 + img * POST_N + s] = sc;
    }
}

// ================= launch ====================
extern "C" void kernel_launch(void* const* d_in, const int* in_sizes, int n_in,
                              void* d_out, int out_size) {
    const float*  obj     = (const float*) d_in[0];   // [4, 159882]
    const float4* deltas  = (const float4*)d_in[1];   // [4, 159882, 4]
    const float4* anchors = (const float4*)d_in[2];   // [159882, 4]
    float* out = (float*)d_out;                       // boxes[4,1000,4] ++ scores[4,1000]

    cudaFuncSetAttribute(topk_kernel,  cudaFuncAttributeMaxDynamicSharedMemorySize, 65536);
    cudaFuncSetAttribute(final_kernel, cudaFuncAttributeMaxDynamicSharedMemorySize, 65536);

    int* selidx;
    cudaGetSymbolAddress((void**)&selidx, g_selidx);

    topk_kernel<<<BATCH * NLEV, 1024, 65536>>>(obj, selidx);
    decode_kernel<<<(BATCH * K_ALL + 255) / 256, 256>>>(obj, deltas, anchors);
    nms_kernel<<<BATCH * NLEV, 1024>>>();
    final_kernel<<<BATCH, 1024, 65536>>>(out);
}

// round 9
// speedup vs baseline: 1.9165x; 1.9137x over previous
#include <cuda_runtime.h>
#include <math.h>

// ---------------- static configuration ----------------
#define BATCH   4
#define A_TOTAL 159882
#define NLEV    5
#define K_ALL   4507
#define POST_N  1000
#define IMG_WF  800.0f
#define IMG_HF  800.0f
#define MIN_SZ  0.001f
#define NMS_T   0.7f
#define BBOX_CLIP 4.135166556742356f
#define FILL_RB 125          // row-blocks of 8 rows per (img,lev)
#define NW      16           // 64-bit words per suppression row (ceil(1000/64))

__constant__ int c_n[NLEV]    = {120000, 30000, 7500, 1875, 507};
__constant__ int c_off[NLEV]  = {0, 120000, 150000, 157500, 159375};
__constant__ int c_k[NLEV]    = {1000, 1000, 1000, 1000, 507};
__constant__ int c_soff[NLEV] = {0, 1000, 2000, 3000, 4000};

// ---------------- scratch (device globals; no allocation) ----------------
__device__ int                g_selidx[BATCH * K_ALL];
__device__ float4             g_boxv  [BATCH * K_ALL];   // clipped boxes
__device__ float              g_scorev[BATCH * K_ALL];   // sigmoid scores
__device__ unsigned           g_keyv  [BATCH * K_ALL];   // mono(obj) if valid else 0
__device__ int                g_maxc  [BATCH];           // float bits (coords >= 0)
__device__ unsigned long long g_sup   [BATCH * NLEV * 1000 * NW];  // 2.56MB
__device__ unsigned long long g_keepbits[BATCH * NLEV * NW];

__device__ __forceinline__ unsigned mono_bits(float f) {
    unsigned u = __float_as_uint(f);
    return (u & 0x80000000u) ? ~u : (u | 0x80000000u);
}

// in-shared-memory bitonic sort, descending, m = power of 2
__device__ __forceinline__ void bitonic_desc(unsigned long long* keys, int m, int t, int NT) {
    for (int k = 2; k <= m; k <<= 1) {
        for (int j = k >> 1; j > 0; j >>= 1) {
            for (int i = t; i < m; i += NT) {
                int ix = i ^ j;
                if (ix > i) {
                    unsigned long long a = keys[i], b = keys[ix];
                    bool desc = ((i & k) == 0);
                    if (desc ? (a < b) : (a > b)) { keys[i] = b; keys[ix] = a; }
                }
            }
            __syncthreads();
        }
    }
}

extern __shared__ unsigned char dynsm[];

// ================= Kernel 1: per-(image,level) exact top-k =================
// hist(12-bit prefix of monotone key) -> parallel suffix scan finds threshold
// bucket -> compact superset -> bitonic sort on (key, ~idx) -> take k.
__global__ void __launch_bounds__(1024, 1)
topk_kernel(const float* __restrict__ obj) {
    unsigned long long* cand = (unsigned long long*)dynsm;            // 8192 (64KB)
    unsigned*           hist = (unsigned*)(dynsm + 65536);            // 4096 (16KB)
    int*                sA   = (int*)(dynsm + 65536 + 16384);         // 1024
    int*                sB   = sA + 1024;                             // 1024
    __shared__ int sh_B, sh_cnt;

    const int blk = blockIdx.x;            // 0..19
    const int img = blk / NLEV;
    const int lev = blk % NLEV;
    const int n = c_n[lev], lvoff = c_off[lev], k = c_k[lev], soff = c_soff[lev];
    const float* __restrict__ src = obj + img * A_TOTAL + lvoff;
    const int t = threadIdx.x, NT = blockDim.x;

    if (t == 0 && lev == 0) g_maxc[img] = 0;   // reset for this replay

    for (int b = t; b < 4096; b += NT) hist[b] = 0u;
    __syncthreads();

    for (int j = t; j < n; j += NT) {
        unsigned u = mono_bits(src[j]);
        atomicAdd(&hist[u >> 20], 1u);
    }
    __syncthreads();

    // segment sums (4 buckets each) + parallel suffix-inclusive scan
    {
        int base = t * 4;
        sA[t] = (int)(hist[base] + hist[base + 1] + hist[base + 2] + hist[base + 3]);
    }
    __syncthreads();
    {
        int* pin = sA; int* pout = sB;
        for (int d = 1; d < 1024; d <<= 1) {
            int v = pin[t];
            if (t + d < 1024) v += pin[t + d];
            pout[t] = v;
            __syncthreads();
            int* tmp = pin; pin = pout; pout = tmp;
        }
        int suffIncl  = pin[t];
        int suffAfter = (t < 1023) ? pin[t + 1] : 0;
        if (suffIncl >= k && suffAfter < k) {
            int cum = suffAfter, B = 4 * t;
            for (int bb = 4 * t + 3; bb >= 4 * t; bb--) {
                if (cum + (int)hist[bb] >= k) { B = bb; break; }
                cum += (int)hist[bb];
            }
            sh_B = B;
            sh_cnt = 0;
        }
    }
    __syncthreads();

    const int B = sh_B;
    for (int j = t; j < n; j += NT) {
        unsigned u = mono_bits(src[j]);
        if ((int)(u >> 20) >= B) {
            int p = atomicAdd(&sh_cnt, 1);
            if (p < 8192)
                cand[p] = ((unsigned long long)u << 32) | (unsigned)(~(unsigned)j);
        }
    }
    __syncthreads();

    int cnt = sh_cnt;
    if (cnt > 8192) cnt = 8192;
    int m = 1;
    while (m < cnt || m < k) m <<= 1;
    if (m > 8192) m = 8192;
    for (int i = cnt + t; i < m; i += NT) cand[i] = 0ULL;
    __syncthreads();

    bitonic_desc(cand, m, t, NT);

    for (int s = t; s < k; s += NT) {
        int j = (int)(~(unsigned)cand[s]);     // local index (ties asc = lax.top_k)
        g_selidx[img * K_ALL + soff + s] = lvoff + j;
    }
}

// ================= Kernel 2: gather + decode + clip + valid + max_coord =====
__global__ void decode_kernel(const float* __restrict__ obj,
                              const float4* __restrict__ deltas,
                              const float4* __restrict__ anchors) {
    int g = blockIdx.x * blockDim.x + threadIdx.x;
    if (g >= BATCH * K_ALL) return;
    int img = g / K_ALL;
    int idx = g_selidx[g];

    float  o = obj[img * A_TOTAL + idx];
    float4 d = deltas[img * A_TOTAL + idx];
    float4 a = anchors[idx];

    float wa  = __fsub_rn(a.z, a.x);
    float ha  = __fsub_rn(a.w, a.y);
    float cxa = __fadd_rn(a.x, __fmul_rn(0.5f, wa));
    float cya = __fadd_rn(a.y, __fmul_rn(0.5f, ha));
    float dw  = fminf(d.z, BBOX_CLIP);
    float dh  = fminf(d.w, BBOX_CLIP);
    float cx  = __fadd_rn(__fmul_rn(d.x, wa), cxa);
    float cy  = __fadd_rn(__fmul_rn(d.y, ha), cya);
    float w   = __fmul_rn(expf(dw), wa);
    float h   = __fmul_rn(expf(dh), ha);
    float x1  = __fsub_rn(cx, __fmul_rn(0.5f, w));
    float y1  = __fsub_rn(cy, __fmul_rn(0.5f, h));
    float x2  = __fadd_rn(cx, __fmul_rn(0.5f, w));
    float y2  = __fadd_rn(cy, __fmul_rn(0.5f, h));

    float x1c = fminf(fmaxf(x1, 0.0f), IMG_WF);
    float y1c = fminf(fmaxf(y1, 0.0f), IMG_HF);
    float x2c = fminf(fmaxf(x2, 0.0f), IMG_WF);
    float y2c = fminf(fmaxf(y2, 0.0f), IMG_HF);

    float score = 1.0f / (1.0f + expf(-o));
    bool valid = (__fsub_rn(x2c, x1c) >= MIN_SZ) &&
                 (__fsub_rn(y2c, y1c) >= MIN_SZ) &&
                 (score >= 0.0f);

    g_boxv[g]   = make_float4(x1c, y1c, x2c, y2c);
    g_scorev[g] = score;
    g_keyv[g]   = valid ? mono_bits(o) : 0u;

    float mx = fmaxf(fmaxf(x1c, y1c), fmaxf(x2c, y2c));
    atomicMax(&g_maxc[img], __float_as_int(mx));
}

// ================= Kernel 3a: suppression matrix fill (all SMs) =============
__device__ __forceinline__ bool pair_sup(float4 bi, float ai,
                                         const float4* sbox, const float* sar,
                                         int j, int i, int k) {
    if (j <= i || j >= k) return false;
    float4 bj = sbox[j];
    float lx = fmaxf(bi.x, bj.x), ly = fmaxf(bi.y, bj.y);
    float rx = fminf(bi.z, bj.z), ry = fminf(bi.w, bj.w);
    float ww = fmaxf(__fsub_rn(rx, lx), 0.0f);
    float hh = fmaxf(__fsub_rn(ry, ly), 0.0f);
    float inter = __fmul_rn(ww, hh);
    if (!(inter > 0.0f)) return false;                 // ref: 0/denom=0 or 0/0=NaN -> false
    float denom = __fsub_rn(__fadd_rn(ai, sar[j]), inter);
    float hib = __fmul_rn(denom, 0.7000070f);
    float lob = __fmul_rn(denom, 0.6999930f);
    if (inter > hib && denom >= 0.0f) return true;     // certified > 0.7 (covers denom==0 -> +inf)
    if (inter < lob) return false;                     // certified <= 0.7
    return __fdiv_rn(inter, denom) > NMS_T;            // exact boundary / denom<0 path
}

__global__ void __launch_bounds__(256)
nms_fill_kernel() {
    const int bid  = blockIdx.x;
    const int inst = bid / FILL_RB;            // img*NLEV + lev
    const int rb   = bid % FILL_RB;
    const int img  = inst / NLEV, lev = inst % NLEV;
    const int k = c_k[lev], soff = c_soff[lev];
    if (rb * 8 >= k) return;
    const int base = img * K_ALL + soff;

    __shared__ float4 sbox[1000];
    __shared__ float  sar [1000];

    float maxc = __int_as_float(g_maxc[img]);
    float off  = __fmul_rn((float)lev, __fadd_rn(maxc, 1.0f));

    for (int j = threadIdx.x; j < k; j += 256) {
        float4 b = g_boxv[base + j];
        float x1 = __fadd_rn(b.x, off), y1 = __fadd_rn(b.y, off);
        float x2 = __fadd_rn(b.z, off), y2 = __fadd_rn(b.w, off);
        sbox[j] = make_float4(x1, y1, x2, y2);
        sar[j]  = __fmul_rn(__fsub_rn(x2, x1), __fsub_rn(y2, y1));
    }
    __syncthreads();

    const int warp = threadIdx.x >> 5, lane = threadIdx.x & 31;
    const int i = rb * 8 + warp;
    if (i >= k) return;
    float4 bi = sbox[i];
    float  ai = sar[i];
    unsigned long long* dst = &g_sup[(size_t)(inst * 1000 + i) * NW];

    for (int w = 0; w < NW; w++) {
        if (w * 64 + 63 <= i) {                  // whole word below/at diagonal
            if (lane == 0) dst[w] = 0ULL;
            continue;
        }
        int j0 = w * 64 + lane;
        bool bA = pair_sup(bi, ai, sbox, sar, j0,      i, k);
        bool bB = pair_sup(bi, ai, sbox, sar, j0 + 32, i, k);
        unsigned m0 = __ballot_sync(0xffffffffu, bA);
        unsigned m1 = __ballot_sync(0xffffffffu, bB);
        if (lane == 0) dst[w] = (unsigned long long)m0 | ((unsigned long long)m1 << 32);
    }
}

// ================= Kernel 3b: greedy scan over bit matrix ===================
__global__ void __launch_bounds__(1024, 1)
nms_scan_kernel() {
    unsigned long long* ssup = (unsigned long long*)dynsm;   // k*NW words (<=128000B)
    __shared__ unsigned sball[32];

    const int inst = blockIdx.x;
    const int img = inst / NLEV, lev = inst % NLEV;
    const int k = c_k[lev], soff = c_soff[lev];
    const int base = img * K_ALL + soff;
    const int t = threadIdx.x;

    const unsigned long long* src = &g_sup[(size_t)inst * 1000 * NW];
    const int tot = k * NW;
    for (int x = t; x < tot; x += 1024) ssup[x] = src[x];

    bool valid = (t < k) && (g_keyv[base + t] != 0u);
    unsigned bm = __ballot_sync(0xffffffffu, valid);
    if ((t & 31) == 0) sball[t >> 5] = bm;
    __syncthreads();

    if (t == 0) {
        unsigned long long keep[NW];
        #pragma unroll
        for (int q = 0; q < NW; q++)
            keep[q] = (unsigned long long)sball[2 * q] |
                      ((unsigned long long)sball[2 * q + 1] << 32);
        int i = 0;
        while (i < k) {
            unsigned long long w = keep[i >> 6] >> (i & 63);
            if (w == 0ULL) { i = ((i >> 6) + 1) << 6; continue; }
            i += __ffsll((long long)w) - 1;
            if (i >= k) break;
            const unsigned long long* row = &ssup[i * NW];
            #pragma unroll
            for (int q = 0; q < NW; q++) keep[q] &= ~row[q];
            i++;
        }
        #pragma unroll
        for (int q = 0; q < NW; q++) g_keepbits[inst * NW + q] = keep[q];
    }
}

// ================= Kernel 4: rank kept candidates via 5-way merge ===========
// Per-level kept lists are already strictly descending in the composite key
// (mono(obj)<<32 | ~slot). Global rank = own position + binary searches.
__global__ void __launch_bounds__(1024, 1)
final_kernel(float* __restrict__ out) {
    __shared__ unsigned long long klist[K_ALL];
    __shared__ int lvbase[NLEV + 1];
    __shared__ int warpsum[32];

    const int img = blockIdx.x;
    const int t = threadIdx.x;
    const int wid = t >> 5, lane = t & 31;

    // zero outputs for this image
    for (int x = t; x < POST_N * 4; x += 1024) out[img * POST_N * 4 + x] = 0.0f;
    for (int x = t; x < POST_N; x += 1024) out[BATCH * POST_N * 4 + img * POST_N + x] = 0.0f;
    if (t == 0) lvbase[0] = 0;
    __syncthreads();

    for (int lev = 0; lev < NLEV; lev++) {
        const int k = c_k[lev], soff = c_soff[lev];
        bool kept = false;
        unsigned long long key = 0ULL;
        if (t < k) {
            unsigned long long kb = g_keepbits[(img * NLEV + lev) * NW + (t >> 6)];
            if ((kb >> (t & 63)) & 1ULL) {
                int slot = soff + t;
                kept = true;
                key = ((unsigned long long)g_keyv[img * K_ALL + slot] << 32) |
                      (unsigned)(~(unsigned)slot);
            }
        }
        unsigned bm = __ballot_sync(0xffffffffu, kept);
        if (lane == 0) warpsum[wid] = __popc(bm);
        __syncthreads();
        if (t < 32) {
            int v = warpsum[t];
            for (int d = 1; d < 32; d <<= 1) {
                int o = __shfl_up_sync(0xffffffffu, v, d);
                if (t >= d) v += o;
            }
            warpsum[t] = v;   // inclusive
            if (t == 31) lvbase[lev + 1] = lvbase[lev] + v;
        }
        __syncthreads();
        if (kept) {
            int pos = lvbase[lev] + (wid ? warpsum[wid - 1] : 0) +
                      __popc(bm & ((1u << lane) - 1u));
            klist[pos] = key;
        }
        __syncthreads();
    }

    const int C = lvbase[NLEV];
    for (int c = t; c < C; c += 1024) {
        int lev = 0;
        while (lev < NLEV - 1 && c >= lvbase[lev + 1]) lev++;
        unsigned long long key = klist[c];
        int rank = c - lvbase[lev];
        for (int l2 = 0; l2 < NLEV; l2++) {
            if (l2 == lev) continue;
            int lo = lvbase[l2], hi = lvbase[l2 + 1];
            while (lo < hi) {
                int mid = (lo + hi) >> 1;
                if (klist[mid] > key) lo = mid + 1; else hi = mid;
            }
            rank += lo - lvbase[l2];
        }
        if (rank < POST_N) {
            int slot = (int)(~(unsigned)key);
            float4 b = g_boxv[img * K_ALL + slot];
            float sc = g_scorev[img * K_ALL + slot];
            float* ob = out + (size_t)(img * POST_N + rank) * 4;
            ob[0] = b.x; ob[1] = b.y; ob[2] = b.z; ob[3] = b.w;
            out[BATCH * POST_N * 4 + img * POST_N + rank] = sc;
        }
    }
}

// ================= launch ====================
extern "C" void kernel_launch(void* const* d_in, const int* in_sizes, int n_in,
                              void* d_out, int out_size) {
    const float*  obj     = (const float*) d_in[0];   // [4, 159882]
    const float4* deltas  = (const float4*)d_in[1];   // [4, 159882, 4]
    const float4* anchors = (const float4*)d_in[2];   // [159882, 4]
    float* out = (float*)d_out;                       // boxes[4,1000,4] ++ scores[4,1000]

    cudaFuncSetAttribute(topk_kernel,     cudaFuncAttributeMaxDynamicSharedMemorySize, 98304);
    cudaFuncSetAttribute(nms_scan_kernel, cudaFuncAttributeMaxDynamicSharedMemorySize, 131072);

    topk_kernel<<<BATCH * NLEV, 1024, 98304>>>(obj);
    decode_kernel<<<(BATCH * K_ALL + 255) / 256, 256>>>(obj, deltas, anchors);
    nms_fill_kernel<<<BATCH * NLEV * FILL_RB, 256>>>();
    nms_scan_kernel<<<BATCH * NLEV, 1024, 128000>>>();
    final_kernel<<<BATCH, 1024>>>(out);
}

// round 10
// speedup vs baseline: 2.6816x; 1.3992x over previous
#include <cuda_runtime.h>
#include <math.h>

// ---------------- static configuration ----------------
#define BATCH   4
#define A_TOTAL 159882
#define NLEV    5
#define K_ALL   4507
#define POST_N  1000
#define IMG_WF  800.0f
#define IMG_HF  800.0f
#define MIN_SZ  0.001f
#define NMS_T   0.7f
#define BBOX_CLIP 4.135166556742356f
#define FILL_RB 32           // row-blocks of 32 rows per (img,lev)
#define NW      16           // 64-bit words per suppression row (ceil(1000/64))
#define NINST   (BATCH * NLEV)

__constant__ int c_n[NLEV]    = {120000, 30000, 7500, 1875, 507};
__constant__ int c_off[NLEV]  = {0, 120000, 150000, 157500, 159375};
__constant__ int c_k[NLEV]    = {1000, 1000, 1000, 1000, 507};
__constant__ int c_soff[NLEV] = {0, 1000, 2000, 3000, 4000};

// ---------------- scratch (device globals; no allocation) ----------------
__device__ unsigned           g_hist  [NINST * 4096];
__device__ int                g_selidx[BATCH * K_ALL];
__device__ float4             g_boxv  [BATCH * K_ALL];   // clipped boxes
__device__ float              g_scorev[BATCH * K_ALL];   // sigmoid scores
__device__ unsigned           g_keyv  [BATCH * K_ALL];   // mono(obj) if valid else 0
__device__ int                g_maxc  [BATCH];           // float bits (coords >= 0)
__device__ unsigned long long g_sup   [NINST * 1000 * NW];
__device__ unsigned           g_rowmask[NINST * 1000];   // nonzero-word mask per row
__device__ unsigned long long g_keepbits[NINST * NW];

__device__ __forceinline__ unsigned mono_bits(float f) {
    unsigned u = __float_as_uint(f);
    return (u & 0x80000000u) ? ~u : (u | 0x80000000u);
}

// in-shared-memory bitonic sort, descending, m = power of 2
__device__ __forceinline__ void bitonic_desc(unsigned long long* keys, int m, int t, int NT) {
    for (int k = 2; k <= m; k <<= 1) {
        for (int j = k >> 1; j > 0; j >>= 1) {
            for (int i = t; i < m; i += NT) {
                int ix = i ^ j;
                if (ix > i) {
                    unsigned long long a = keys[i], b = keys[ix];
                    bool desc = ((i & k) == 0);
                    if (desc ? (a < b) : (a > b)) { keys[i] = b; keys[ix] = a; }
                }
            }
            __syncthreads();
        }
    }
}

extern __shared__ unsigned char dynsm[];

// ================= Kernel 0: flat histogram (all SMs, global RED) ==========
__global__ void __launch_bounds__(256)
hist_kernel(const float* __restrict__ obj) {
    int g = blockIdx.x * 256 + threadIdx.x;
    if (g >= BATCH * A_TOTAL) return;
    int img = g / A_TOTAL;
    int r = g - img * A_TOTAL;
    int lev = (r < 120000) ? 0 : (r < 150000) ? 1 : (r < 157500) ? 2 :
              (r < 159375) ? 3 : 4;
    unsigned u = mono_bits(obj[g]);
    atomicAdd(&g_hist[(img * NLEV + lev) * 4096 + (u >> 20)], 1u);
}

// ================= Kernel 1: per-(image,level) select + compact + sort =====
__global__ void __launch_bounds__(1024, 1)
select_kernel(const float* __restrict__ obj) {
    unsigned long long* cand = (unsigned long long*)dynsm;            // 8192 (64KB)
    unsigned*           hist = (unsigned*)(dynsm + 65536);            // 4096 (16KB)
    int*                sA   = (int*)(dynsm + 65536 + 16384);         // 1024
    int*                sB   = sA + 1024;                             // 1024
    __shared__ int sh_B, sh_cnt;

    const int inst = blockIdx.x;           // 0..19
    const int img = inst / NLEV;
    const int lev = inst % NLEV;
    const int n = c_n[lev], lvoff = c_off[lev], k = c_k[lev], soff = c_soff[lev];
    const float* __restrict__ src = obj + img * A_TOTAL + lvoff;
    const int t = threadIdx.x, NT = blockDim.x;

    for (int b = t; b < 4096; b += NT) hist[b] = g_hist[inst * 4096 + b];
    __syncthreads();

    // segment sums (4 buckets each) + parallel suffix-inclusive scan
    {
        int base = t * 4;
        sA[t] = (int)(hist[base] + hist[base + 1] + hist[base + 2] + hist[base + 3]);
    }
    __syncthreads();
    {
        int* pin = sA; int* pout = sB;
        for (int d = 1; d < 1024; d <<= 1) {
            int v = pin[t];
            if (t + d < 1024) v += pin[t + d];
            pout[t] = v;
            __syncthreads();
            int* tmp = pin; pin = pout; pout = tmp;
        }
        int suffIncl  = pin[t];
        int suffAfter = (t < 1023) ? pin[t + 1] : 0;
        if (suffIncl >= k && suffAfter < k) {
            int cum = suffAfter, B = 4 * t;
            for (int bb = 4 * t + 3; bb >= 4 * t; bb--) {
                if (cum + (int)hist[bb] >= k) { B = bb; break; }
                cum += (int)hist[bb];
            }
            sh_B = B;
            sh_cnt = 0;
        }
    }
    __syncthreads();

    const int B = sh_B;
    for (int j = t; j < n; j += NT) {
        unsigned u = mono_bits(src[j]);
        if ((int)(u >> 20) >= B) {
            int p = atomicAdd(&sh_cnt, 1);
            if (p < 8192)
                cand[p] = ((unsigned long long)u << 32) | (unsigned)(~(unsigned)j);
        }
    }
    __syncthreads();

    int cnt = sh_cnt;
    if (cnt > 8192) cnt = 8192;
    int m = 1;
    while (m < cnt || m < k) m <<= 1;
    if (m > 8192) m = 8192;
    for (int i = cnt + t; i < m; i += NT) cand[i] = 0ULL;
    __syncthreads();

    bitonic_desc(cand, m, t, NT);

    for (int s = t; s < k; s += NT) {
        int j = (int)(~(unsigned)cand[s]);     // local index (ties asc = lax.top_k)
        g_selidx[img * K_ALL + soff + s] = lvoff + j;
    }
}

// ================= Kernel 2: gather + decode + clip + valid + max_coord =====
__global__ void decode_kernel(const float* __restrict__ obj,
                              const float4* __restrict__ deltas,
                              const float4* __restrict__ anchors) {
    int g = blockIdx.x * blockDim.x + threadIdx.x;
    if (g >= BATCH * K_ALL) return;
    int img = g / K_ALL;
    int idx = g_selidx[g];

    float  o = obj[img * A_TOTAL + idx];
    float4 d = deltas[img * A_TOTAL + idx];
    float4 a = anchors[idx];

    float wa  = __fsub_rn(a.z, a.x);
    float ha  = __fsub_rn(a.w, a.y);
    float cxa = __fadd_rn(a.x, __fmul_rn(0.5f, wa));
    float cya = __fadd_rn(a.y, __fmul_rn(0.5f, ha));
    float dw  = fminf(d.z, BBOX_CLIP);
    float dh  = fminf(d.w, BBOX_CLIP);
    float cx  = __fadd_rn(__fmul_rn(d.x, wa), cxa);
    float cy  = __fadd_rn(__fmul_rn(d.y, ha), cya);
    float w   = __fmul_rn(expf(dw), wa);
    float h   = __fmul_rn(expf(dh), ha);
    float x1  = __fsub_rn(cx, __fmul_rn(0.5f, w));
    float y1  = __fsub_rn(cy, __fmul_rn(0.5f, h));
    float x2  = __fadd_rn(cx, __fmul_rn(0.5f, w));
    float y2  = __fadd_rn(cy, __fmul_rn(0.5f, h));

    float x1c = fminf(fmaxf(x1, 0.0f), IMG_WF);
    float y1c = fminf(fmaxf(y1, 0.0f), IMG_HF);
    float x2c = fminf(fmaxf(x2, 0.0f), IMG_WF);
    float y2c = fminf(fmaxf(y2, 0.0f), IMG_HF);

    float score = 1.0f / (1.0f + expf(-o));
    bool valid = (__fsub_rn(x2c, x1c) >= MIN_SZ) &&
                 (__fsub_rn(y2c, y1c) >= MIN_SZ) &&
                 (score >= 0.0f);

    g_boxv[g]   = make_float4(x1c, y1c, x2c, y2c);
    g_scorev[g] = score;
    g_keyv[g]   = valid ? mono_bits(o) : 0u;

    float mx = fmaxf(fmaxf(x1c, y1c), fmaxf(x2c, y2c));
    atomicMax(&g_maxc[img], __float_as_int(mx));
}

// ================= Kernel 3a: suppression matrix fill (all SMs) =============
__device__ __forceinline__ bool pair_sup(float4 bi, float ai,
                                         const float4* sbox, const float* sar,
                                         int j, int i, int k) {
    if (j <= i || j >= k) return false;
    float4 bj = sbox[j];
    float lx = fmaxf(bi.x, bj.x), ly = fmaxf(bi.y, bj.y);
    float rx = fminf(bi.z, bj.z), ry = fminf(bi.w, bj.w);
    float ww = fmaxf(__fsub_rn(rx, lx), 0.0f);
    float hh = fmaxf(__fsub_rn(ry, ly), 0.0f);
    float inter = __fmul_rn(ww, hh);
    if (!(inter > 0.0f)) return false;                 // ref: 0/denom=0 or 0/0=NaN -> false
    float denom = __fsub_rn(__fadd_rn(ai, sar[j]), inter);
    float hib = __fmul_rn(denom, 0.7000070f);
    float lob = __fmul_rn(denom, 0.6999930f);
    if (inter > hib && denom >= 0.0f) return true;     // certified > 0.7
    if (inter < lob) return false;                     // certified <= 0.7
    return __fdiv_rn(inter, denom) > NMS_T;            // exact boundary path
}

__global__ void __launch_bounds__(1024)
nms_fill_kernel() {
    const int bid  = blockIdx.x;
    const int inst = bid / FILL_RB;            // img*NLEV + lev
    const int rb   = bid % FILL_RB;
    const int img  = inst / NLEV, lev = inst % NLEV;
    const int k = c_k[lev], soff = c_soff[lev];
    if (rb * 32 >= k) return;
    const int base = img * K_ALL + soff;

    __shared__ float4 sbox[1000];
    __shared__ float  sar [1000];

    float maxc = __int_as_float(g_maxc[img]);
    float off  = __fmul_rn((float)lev, __fadd_rn(maxc, 1.0f));

    for (int j = threadIdx.x; j < k; j += 1024) {
        float4 b = g_boxv[base + j];
        float x1 = __fadd_rn(b.x, off), y1 = __fadd_rn(b.y, off);
        float x2 = __fadd_rn(b.z, off), y2 = __fadd_rn(b.w, off);
        sbox[j] = make_float4(x1, y1, x2, y2);
        sar[j]  = __fmul_rn(__fsub_rn(x2, x1), __fsub_rn(y2, y1));
    }
    __syncthreads();

    const int warp = threadIdx.x >> 5, lane = threadIdx.x & 31;
    const int i = rb * 32 + warp;
    if (i >= k) return;
    float4 bi = sbox[i];
    float  ai = sar[i];
    unsigned long long* dst = &g_sup[(size_t)(inst * 1000 + i) * NW];
    unsigned mask = 0u;

    for (int w = 0; w < NW; w++) {
        if (w * 64 + 63 <= i) continue;          // whole word at/below diagonal
        int j0 = w * 64 + lane;
        bool bA = pair_sup(bi, ai, sbox, sar, j0,      i, k);
        bool bB = pair_sup(bi, ai, sbox, sar, j0 + 32, i, k);
        unsigned m0 = __ballot_sync(0xffffffffu, bA);
        unsigned m1 = __ballot_sync(0xffffffffu, bB);
        unsigned long long wv = (unsigned long long)m0 | ((unsigned long long)m1 << 32);
        if (wv) {
            mask |= 1u << w;
            if (lane == 0) dst[w] = wv;          // write only nonzero words
        }
    }
    if (lane == 0) g_rowmask[inst * 1000 + i] = mask;
}

// ================= Kernel 3b: sparse greedy scan ===========================
// Only kept rows that HAVE suppressors need visiting; all other kept rows
// provably change nothing. The serial chain length is the count of active
// surviving rows (sparse), not k.
__global__ void __launch_bounds__(1024, 1)
nms_scan_kernel() {
    unsigned long long* ssup = (unsigned long long*)dynsm;          // 1000*NW
    unsigned* srm = (unsigned*)(dynsm + 1000 * NW * 8);             // 1000 u32
    __shared__ unsigned sv[32], sa[32];

    const int inst = blockIdx.x;
    const int img = inst / NLEV, lev = inst % NLEV;
    const int k = c_k[lev], soff = c_soff[lev];
    const int base = img * K_ALL + soff;
    const int t = threadIdx.x;

    const unsigned long long* src = &g_sup[(size_t)inst * 1000 * NW];
    const int tot = k * NW;
    for (int x = t; x < tot; x += 1024) ssup[x] = src[x];

    bool valid = false, act = false;
    if (t < k) {
        valid = (g_keyv[base + t] != 0u);
        unsigned m = g_rowmask[inst * 1000 + t];
        srm[t] = m;
        act = (m != 0u);
    }
    unsigned bv = __ballot_sync(0xffffffffu, valid);
    unsigned ba = __ballot_sync(0xffffffffu, act);
    if ((t & 31) == 0) { sv[t >> 5] = bv; sa[t >> 5] = ba; }
    __syncthreads();

    if (t == 0) {
        unsigned long long keep[NW];
        #pragma unroll
        for (int q = 0; q < NW; q++)
            keep[q] = (unsigned long long)sv[2 * q] |
                      ((unsigned long long)sv[2 * q + 1] << 32);
        for (int w = 0; w < NW; w++) {
            unsigned long long aw = (unsigned long long)sa[2 * w] |
                                    ((unsigned long long)sa[2 * w + 1] << 32);
            unsigned long long rem = keep[w] & aw;
            while (rem) {
                int b = __ffsll((long long)rem) - 1;
                int i = w * 64 + b;
                unsigned m = srm[i];
                const unsigned long long* row = &ssup[i * NW];
                while (m) {
                    int q = __ffs(m) - 1;
                    m &= m - 1u;
                    keep[q] &= ~row[q];
                }
                unsigned long long higher = (b == 63) ? 0ULL : (~0ULL << (b + 1));
                rem = keep[w] & aw & higher;
            }
        }
        #pragma unroll
        for (int q = 0; q < NW; q++) g_keepbits[inst * NW + q] = keep[q];
    }
}

// ================= Kernel 4: rank kept candidates via 5-way merge ===========
__global__ void __launch_bounds__(1024, 1)
final_kernel(float* __restrict__ out) {
    __shared__ unsigned long long klist[K_ALL];
    __shared__ int lvbase[NLEV + 1];
    __shared__ int warpsum[32];

    const int img = blockIdx.x;
    const int t = threadIdx.x;
    const int wid = t >> 5, lane = t & 31;

    for (int x = t; x < POST_N * 4; x += 1024) out[img * POST_N * 4 + x] = 0.0f;
    for (int x = t; x < POST_N; x += 1024) out[BATCH * POST_N * 4 + img * POST_N + x] = 0.0f;
    if (t == 0) lvbase[0] = 0;
    __syncthreads();

    for (int lev = 0; lev < NLEV; lev++) {
        const int k = c_k[lev], soff = c_soff[lev];
        bool kept = false;
        unsigned long long key = 0ULL;
        if (t < k) {
            unsigned long long kb = g_keepbits[(img * NLEV + lev) * NW + (t >> 6)];
            if ((kb >> (t & 63)) & 1ULL) {
                int slot = soff + t;
                kept = true;
                key = ((unsigned long long)g_keyv[img * K_ALL + slot] << 32) |
                      (unsigned)(~(unsigned)slot);
            }
        }
        unsigned bm = __ballot_sync(0xffffffffu, kept);
        if (lane == 0) warpsum[wid] = __popc(bm);
        __syncthreads();
        if (t < 32) {
            int v = warpsum[t];
            for (int d = 1; d < 32; d <<= 1) {
                int o = __shfl_up_sync(0xffffffffu, v, d);
                if (t >= d) v += o;
            }
            warpsum[t] = v;   // inclusive
            if (t == 31) lvbase[lev + 1] = lvbase[lev] + v;
        }
        __syncthreads();
        if (kept) {
            int pos = lvbase[lev] + (wid ? warpsum[wid - 1] : 0) +
                      __popc(bm & ((1u << lane) - 1u));
            klist[pos] = key;
        }
        __syncthreads();
    }

    const int C = lvbase[NLEV];
    for (int c = t; c < C; c += 1024) {
        int lev = 0;
        while (lev < NLEV - 1 && c >= lvbase[lev + 1]) lev++;
        unsigned long long key = klist[c];
        int rank = c - lvbase[lev];
        for (int l2 = 0; l2 < NLEV; l2++) {
            if (l2 == lev) continue;
            int lo = lvbase[l2], hi = lvbase[l2 + 1];
            while (lo < hi) {
                int mid = (lo + hi) >> 1;
                if (klist[mid] > key) lo = mid + 1; else hi = mid;
            }
            rank += lo - lvbase[l2];
        }
        if (rank < POST_N) {
            int slot = (int)(~(unsigned)key);
            float4 b = g_boxv[img * K_ALL + slot];
            float sc = g_scorev[img * K_ALL + slot];
            float* ob = out + (size_t)(img * POST_N + rank) * 4;
            ob[0] = b.x; ob[1] = b.y; ob[2] = b.z; ob[3] = b.w;
            out[BATCH * POST_N * 4 + img * POST_N + rank] = sc;
        }
    }
}

// ================= launch ====================
extern "C" void kernel_launch(void* const* d_in, const int* in_sizes, int n_in,
                              void* d_out, int out_size) {
    const float*  obj     = (const float*) d_in[0];   // [4, 159882]
    const float4* deltas  = (const float4*)d_in[1];   // [4, 159882, 4]
    const float4* anchors = (const float4*)d_in[2];   // [159882, 4]
    float* out = (float*)d_out;                       // boxes[4,1000,4] ++ scores[4,1000]

    cudaFuncSetAttribute(select_kernel,   cudaFuncAttributeMaxDynamicSharedMemorySize, 98304);
    cudaFuncSetAttribute(nms_scan_kernel, cudaFuncAttributeMaxDynamicSharedMemorySize, 135168);

    void* hist_ptr; cudaGetSymbolAddress(&hist_ptr, g_hist);
    void* maxc_ptr; cudaGetSymbolAddress(&maxc_ptr, g_maxc);
    cudaMemsetAsync(hist_ptr, 0, NINST * 4096 * sizeof(unsigned));
    cudaMemsetAsync(maxc_ptr, 0, BATCH * sizeof(int));

    hist_kernel<<<(BATCH * A_TOTAL + 255) / 256, 256>>>(obj);
    select_kernel<<<NINST, 1024, 98304>>>(obj);
    decode_kernel<<<(BATCH * K_ALL + 255) / 256, 256>>>(obj, deltas, anchors);
    nms_fill_kernel<<<NINST * FILL_RB, 1024>>>();
    nms_scan_kernel<<<NINST, 1024, 132096>>>();
    final_kernel<<<BATCH, 1024>>>(out);
}

// round 11
// speedup vs baseline: 2.9679x; 1.1068x over previous
#include <cuda_runtime.h>
#include <math.h>

// ---------------- static configuration ----------------
#define BATCH   4
#define A_TOTAL 159882
#define NLEV    5
#define K_ALL   4507
#define POST_N  1000
#define IMG_WF  800.0f
#define IMG_HF  800.0f
#define MIN_SZ  0.001f
#define NMS_T   0.7f
#define BBOX_CLIP 4.135166556742356f
#define FILL_RB 16           // row-blocks of 64 rows (2 per warp) per (img,lev)
#define NW      16           // 64-bit words per suppression row (ceil(1000/64))
#define NINST   (BATCH * NLEV)

__constant__ int c_n[NLEV]    = {120000, 30000, 7500, 1875, 507};
__constant__ int c_off[NLEV]  = {0, 120000, 150000, 157500, 159375};
__constant__ int c_k[NLEV]    = {1000, 1000, 1000, 1000, 507};
__constant__ int c_soff[NLEV] = {0, 1000, 2000, 3000, 4000};

// ---------------- scratch (device globals; zero-init at load) --------------
__device__ unsigned           g_hist  [NINST * 4096];
__device__ float4             g_boxv  [BATCH * K_ALL];   // clipped boxes
__device__ float              g_scorev[BATCH * K_ALL];   // sigmoid scores
__device__ unsigned           g_keyv  [BATCH * K_ALL];   // mono(obj) if valid else 0
__device__ int                g_maxc  [BATCH];           // float bits (coords >= 0)
__device__ unsigned long long g_sup   [NINST * 1000 * NW];
__device__ unsigned           g_rowmask[NINST * 1000];   // nonzero-word mask per row
__device__ unsigned long long g_keepbits[NINST * NW];

__device__ __forceinline__ unsigned mono_bits(float f) {
    unsigned u = __float_as_uint(f);
    return (u & 0x80000000u) ? ~u : (u | 0x80000000u);
}

// in-shared-memory bitonic sort, descending, m = power of 2
__device__ __forceinline__ void bitonic_desc(unsigned long long* keys, int m, int t, int NT) {
    for (int k = 2; k <= m; k <<= 1) {
        for (int j = k >> 1; j > 0; j >>= 1) {
            for (int i = t; i < m; i += NT) {
                int ix = i ^ j;
                if (ix > i) {
                    unsigned long long a = keys[i], b = keys[ix];
                    bool desc = ((i & k) == 0);
                    if (desc ? (a < b) : (a > b)) { keys[i] = b; keys[ix] = a; }
                }
            }
            __syncthreads();
        }
    }
}

extern __shared__ unsigned char dynsm[];

// ================= Kernel 0: flat histogram (all SMs, global RED) ==========
__global__ void __launch_bounds__(256)
hist_kernel(const float* __restrict__ obj) {
    int base = (blockIdx.x * 256 + threadIdx.x) * 4;
    if (base >= BATCH * A_TOTAL) return;
    #pragma unroll
    for (int e = 0; e < 4; e++) {
        int g = base + e;
        int img = g / A_TOTAL;
        int r = g - img * A_TOTAL;
        int lev = (r < 120000) ? 0 : (r < 150000) ? 1 : (r < 157500) ? 2 :
                  (r < 159375) ? 3 : 4;
        unsigned u = mono_bits(obj[g]);
        atomicAdd(&g_hist[(img * NLEV + lev) * 4096 + (u >> 20)], 1u);
    }
}

// ================= Kernel 1: select + compact + sort + inline decode =======
__global__ void __launch_bounds__(1024, 1)
select_kernel(const float* __restrict__ obj,
              const float4* __restrict__ deltas,
              const float4* __restrict__ anchors) {
    unsigned long long* cand = (unsigned long long*)dynsm;            // 8192 (64KB)
    unsigned*           hist = (unsigned*)(dynsm + 65536);            // 4096 (16KB)
    int*                sA   = (int*)(dynsm + 65536 + 16384);         // 1024
    int*                sB   = sA + 1024;                             // 1024
    __shared__ int sh_B, sh_cnt;

    const int inst = blockIdx.x;           // 0..19
    const int img = inst / NLEV;
    const int lev = inst % NLEV;
    const int n = c_n[lev], lvoff = c_off[lev], k = c_k[lev], soff = c_soff[lev];
    const float* __restrict__ src = obj + img * A_TOTAL + lvoff;
    const int t = threadIdx.x, NT = blockDim.x;

    for (int b = t; b < 4096; b += NT) {
        hist[b] = g_hist[inst * 4096 + b];
        g_hist[inst * 4096 + b] = 0u;       // re-zero for next replay
    }
    __syncthreads();

    // segment sums (4 buckets each) + parallel suffix-inclusive scan
    {
        int base = t * 4;
        sA[t] = (int)(hist[base] + hist[base + 1] + hist[base + 2] + hist[base + 3]);
    }
    __syncthreads();
    {
        int* pin = sA; int* pout = sB;
        for (int d = 1; d < 1024; d <<= 1) {
            int v = pin[t];
            if (t + d < 1024) v += pin[t + d];
            pout[t] = v;
            __syncthreads();
            int* tmp = pin; pin = pout; pout = tmp;
        }
        int suffIncl  = pin[t];
        int suffAfter = (t < 1023) ? pin[t + 1] : 0;
        if (suffIncl >= k && suffAfter < k) {
            int cum = suffAfter, B = 4 * t;
            for (int bb = 4 * t + 3; bb >= 4 * t; bb--) {
                if (cum + (int)hist[bb] >= k) { B = bb; break; }
                cum += (int)hist[bb];
            }
            sh_B = B;
            sh_cnt = 0;
        }
    }
    __syncthreads();

    const int B = sh_B;
    for (int j = t; j < n; j += NT) {
        unsigned u = mono_bits(src[j]);
        if ((int)(u >> 20) >= B) {
            int p = atomicAdd(&sh_cnt, 1);
            if (p < 8192)
                cand[p] = ((unsigned long long)u << 32) | (unsigned)(~(unsigned)j);
        }
    }
    __syncthreads();

    int cnt = sh_cnt;
    if (cnt > 8192) cnt = 8192;
    int m = 1;
    while (m < cnt || m < k) m <<= 1;
    if (m > 8192) m = 8192;
    for (int i = cnt + t; i < m; i += NT) cand[i] = 0ULL;
    __syncthreads();

    bitonic_desc(cand, m, t, NT);

    // inline decode of the k selected candidates
    for (int s = t; s < k; s += NT) {
        int j = (int)(~(unsigned)cand[s]);     // local index (ties asc = lax.top_k)
        int idx = lvoff + j;
        int g = img * K_ALL + soff + s;

        float  o = obj[img * A_TOTAL + idx];
        float4 d = deltas[img * A_TOTAL + idx];
        float4 a = anchors[idx];

        float wa  = __fsub_rn(a.z, a.x);
        float ha  = __fsub_rn(a.w, a.y);
        float cxa = __fadd_rn(a.x, __fmul_rn(0.5f, wa));
        float cya = __fadd_rn(a.y, __fmul_rn(0.5f, ha));
        float dw  = fminf(d.z, BBOX_CLIP);
        float dh  = fminf(d.w, BBOX_CLIP);
        float cx  = __fadd_rn(__fmul_rn(d.x, wa), cxa);
        float cy  = __fadd_rn(__fmul_rn(d.y, ha), cya);
        float w   = __fmul_rn(expf(dw), wa);
        float h   = __fmul_rn(expf(dh), ha);
        float x1  = __fsub_rn(cx, __fmul_rn(0.5f, w));
        float y1  = __fsub_rn(cy, __fmul_rn(0.5f, h));
        float x2  = __fadd_rn(cx, __fmul_rn(0.5f, w));
        float y2  = __fadd_rn(cy, __fmul_rn(0.5f, h));

        float x1c = fminf(fmaxf(x1, 0.0f), IMG_WF);
        float y1c = fminf(fmaxf(y1, 0.0f), IMG_HF);
        float x2c = fminf(fmaxf(x2, 0.0f), IMG_WF);
        float y2c = fminf(fmaxf(y2, 0.0f), IMG_HF);

        float score = 1.0f / (1.0f + expf(-o));
        bool valid = (__fsub_rn(x2c, x1c) >= MIN_SZ) &&
                     (__fsub_rn(y2c, y1c) >= MIN_SZ) &&
                     (score >= 0.0f);

        g_boxv[g]   = make_float4(x1c, y1c, x2c, y2c);
        g_scorev[g] = score;
        g_keyv[g]   = valid ? mono_bits(o) : 0u;

        float mx = fmaxf(fmaxf(x1c, y1c), fmaxf(x2c, y2c));
        atomicMax(&g_maxc[img], __float_as_int(mx));
    }
}

// ================= Kernel 2: suppression matrix fill (all SMs) =============
__device__ __forceinline__ bool pair_sup(float4 bi, float ai,
                                         const float4* sbox, const float* sar,
                                         int j, int i, int k) {
    if (j <= i || j >= k) return false;
    float4 bj = sbox[j];
    float lx = fmaxf(bi.x, bj.x), ly = fmaxf(bi.y, bj.y);
    float rx = fminf(bi.z, bj.z), ry = fminf(bi.w, bj.w);
    float ww = fmaxf(__fsub_rn(rx, lx), 0.0f);
    float hh = fmaxf(__fsub_rn(ry, ly), 0.0f);
    float inter = __fmul_rn(ww, hh);
    if (!(inter > 0.0f)) return false;                 // ref: 0/denom=0 or 0/0=NaN -> false
    float denom = __fsub_rn(__fadd_rn(ai, sar[j]), inter);
    float hib = __fmul_rn(denom, 0.7000070f);
    float lob = __fmul_rn(denom, 0.6999930f);
    if (inter > hib && denom >= 0.0f) return true;     // certified > 0.7
    if (inter < lob) return false;                     // certified <= 0.7
    return __fdiv_rn(inter, denom) > NMS_T;            // exact boundary path
}

__device__ __forceinline__ void fill_row(int i, int k, int inst,
                                         const float4* sbox, const float* sar,
                                         int lane) {
    if (i >= k) return;
    float4 bi = sbox[i];
    float  ai = sar[i];
    unsigned long long* dst = &g_sup[(size_t)(inst * 1000 + i) * NW];
    unsigned mask = 0u;

    for (int w = i >> 6; w < NW; w++) {
        int j0 = w * 64 + lane;
        bool bA = pair_sup(bi, ai, sbox, sar, j0,      i, k);
        bool bB = pair_sup(bi, ai, sbox, sar, j0 + 32, i, k);
        unsigned m0 = __ballot_sync(0xffffffffu, bA);
        unsigned m1 = __ballot_sync(0xffffffffu, bB);
        unsigned long long wv = (unsigned long long)m0 | ((unsigned long long)m1 << 32);
        if (wv) {
            mask |= 1u << w;
            if (lane == 0) dst[w] = wv;          // write only nonzero words
        }
    }
    if (lane == 0) g_rowmask[inst * 1000 + i] = mask;
}

__global__ void __launch_bounds__(1024)
nms_fill_kernel() {
    const int bid  = blockIdx.x;
    const int inst = bid / FILL_RB;            // img*NLEV + lev
    const int rb   = bid % FILL_RB;
    const int img  = inst / NLEV, lev = inst % NLEV;
    const int k = c_k[lev], soff = c_soff[lev];
    if (rb * 64 >= k) return;
    const int base = img * K_ALL + soff;

    __shared__ float4 sbox[1000];
    __shared__ float  sar [1000];

    float maxc = __int_as_float(g_maxc[img]);
    float off  = __fmul_rn((float)lev, __fadd_rn(maxc, 1.0f));

    for (int j = threadIdx.x; j < k; j += 1024) {
        float4 b = g_boxv[base + j];
        float x1 = __fadd_rn(b.x, off), y1 = __fadd_rn(b.y, off);
        float x2 = __fadd_rn(b.z, off), y2 = __fadd_rn(b.w, off);
        sbox[j] = make_float4(x1, y1, x2, y2);
        sar[j]  = __fmul_rn(__fsub_rn(x2, x1), __fsub_rn(y2, y1));
    }
    __syncthreads();

    const int warp = threadIdx.x >> 5, lane = threadIdx.x & 31;
    fill_row(rb * 64 + warp,      k, inst, sbox, sar, lane);
    fill_row(rb * 64 + warp + 32, k, inst, sbox, sar, lane);
}

// ================= Kernel 3: sparse greedy scan ===========================
__global__ void __launch_bounds__(1024, 1)
nms_scan_kernel() {
    unsigned long long* ssup = (unsigned long long*)dynsm;          // 1000*NW
    unsigned* srm = (unsigned*)(dynsm + 1000 * NW * 8);             // 1000 u32
    __shared__ unsigned sv[32], sa[32];

    const int inst = blockIdx.x;
    const int img = inst / NLEV, lev = inst % NLEV;
    const int k = c_k[lev], soff = c_soff[lev];
    const int base = img * K_ALL + soff;
    const int t = threadIdx.x;

    bool valid = false, act = false;
    if (t < k) {
        valid = (g_keyv[base + t] != 0u);
        unsigned m = g_rowmask[inst * 1000 + t];
        srm[t] = m;
        act = (m != 0u);
        // sparse load: only nonzero words of this row
        const unsigned long long* row = &g_sup[(size_t)(inst * 1000 + t) * NW];
        unsigned mm = m;
        while (mm) {
            int q = __ffs(mm) - 1;
            mm &= mm - 1u;
            ssup[t * NW + q] = row[q];
        }
    }
    unsigned bv = __ballot_sync(0xffffffffu, valid);
    unsigned ba = __ballot_sync(0xffffffffu, act);
    if ((t & 31) == 0) { sv[t >> 5] = bv; sa[t >> 5] = ba; }
    __syncthreads();

    if (t == 0) {
        unsigned long long keep[NW];
        #pragma unroll
        for (int q = 0; q < NW; q++)
            keep[q] = (unsigned long long)sv[2 * q] |
                      ((unsigned long long)sv[2 * q + 1] << 32);
        for (int w = 0; w < NW; w++) {
            unsigned long long aw = (unsigned long long)sa[2 * w] |
                                    ((unsigned long long)sa[2 * w + 1] << 32);
            unsigned long long rem = keep[w] & aw;
            while (rem) {
                int b = __ffsll((long long)rem) - 1;
                int i = w * 64 + b;
                unsigned m = srm[i];
                const unsigned long long* row = &ssup[i * NW];
                while (m) {
                    int q = __ffs(m) - 1;
                    m &= m - 1u;
                    keep[q] &= ~row[q];
                }
                unsigned long long higher = (b == 63) ? 0ULL : (~0ULL << (b + 1));
                rem = keep[w] & aw & higher;
            }
        }
        #pragma unroll
        for (int q = 0; q < NW; q++) g_keepbits[inst * NW + q] = keep[q];
    }
}

// ================= Kernel 4: rank kept candidates via 5-way merge ===========
__global__ void __launch_bounds__(1024, 1)
final_kernel(float* __restrict__ out) {
    __shared__ unsigned long long klist[K_ALL];
    __shared__ int lvbase[NLEV + 1];
    __shared__ int warpsum[32];

    const int img = blockIdx.x;
    const int t = threadIdx.x;
    const int wid = t >> 5, lane = t & 31;

    for (int x = t; x < POST_N * 4; x += 1024) out[img * POST_N * 4 + x] = 0.0f;
    for (int x = t; x < POST_N; x += 1024) out[BATCH * POST_N * 4 + img * POST_N + x] = 0.0f;
    if (t == 0) { lvbase[0] = 0; g_maxc[img] = 0; }   // re-zero maxc for next replay
    __syncthreads();

    for (int lev = 0; lev < NLEV; lev++) {
        const int k = c_k[lev], soff = c_soff[lev];
        bool kept = false;
        unsigned long long key = 0ULL;
        if (t < k) {
            unsigned long long kb = g_keepbits[(img * NLEV + lev) * NW + (t >> 6)];
            if ((kb >> (t & 63)) & 1ULL) {
                int slot = soff + t;
                kept = true;
                key = ((unsigned long long)g_keyv[img * K_ALL + slot] << 32) |
                      (unsigned)(~(unsigned)slot);
            }
        }
        unsigned bm = __ballot_sync(0xffffffffu, kept);
        if (lane == 0) warpsum[wid] = __popc(bm);
        __syncthreads();
        if (t < 32) {
            int v = warpsum[t];
            for (int d = 1; d < 32; d <<= 1) {
                int o = __shfl_up_sync(0xffffffffu, v, d);
                if (t >= d) v += o;
            }
            warpsum[t] = v;   // inclusive
            if (t == 31) lvbase[lev + 1] = lvbase[lev] + v;
        }
        __syncthreads();
        if (kept) {
            int pos = lvbase[lev] + (wid ? warpsum[wid - 1] : 0) +
                      __popc(bm & ((1u << lane) - 1u));
            klist[pos] = key;
        }
        __syncthreads();
    }

    const int C = lvbase[NLEV];
    for (int c = t; c < C; c += 1024) {
        int lev = 0;
        while (lev < NLEV - 1 && c >= lvbase[lev + 1]) lev++;
        unsigned long long key = klist[c];
        int rank = c - lvbase[lev];
        for (int l2 = 0; l2 < NLEV; l2++) {
            if (l2 == lev) continue;
            int lo = lvbase[l2], hi = lvbase[l2 + 1];
            while (lo < hi) {
                int mid = (lo + hi) >> 1;
                if (klist[mid] > key) lo = mid + 1; else hi = mid;
            }
            rank += lo - lvbase[l2];
        }
        if (rank < POST_N) {
            int slot = (int)(~(unsigned)key);
            float4 b = g_boxv[img * K_ALL + slot];
            float sc = g_scorev[img * K_ALL + slot];
            float* ob = out + (size_t)(img * POST_N + rank) * 4;
            ob[0] = b.x; ob[1] = b.y; ob[2] = b.z; ob[3] = b.w;
            out[BATCH * POST_N * 4 + img * POST_N + rank] = sc;
        }
    }
}

// ================= launch ====================
extern "C" void kernel_launch(void* const* d_in, const int* in_sizes, int n_in,
                              void* d_out, int out_size) {
    const float*  obj     = (const float*) d_in[0];   // [4, 159882]
    const float4* deltas  = (const float4*)d_in[1];   // [4, 159882, 4]
    const float4* anchors = (const float4*)d_in[2];   // [159882, 4]
    float* out = (float*)d_out;                       // boxes[4,1000,4] ++ scores[4,1000]

    cudaFuncSetAttribute(select_kernel,   cudaFuncAttributeMaxDynamicSharedMemorySize, 98304);
    cudaFuncSetAttribute(nms_scan_kernel, cudaFuncAttributeMaxDynamicSharedMemorySize, 135168);

    const int nelem = BATCH * A_TOTAL;                // 639528, divisible by 4
    hist_kernel<<<(nelem / 4 + 255) / 256, 256>>>(obj);
    select_kernel<<<NINST, 1024, 98304>>>(obj, deltas, anchors);
    nms_fill_kernel<<<NINST * FILL_RB, 1024>>>();
    nms_scan_kernel<<<NINST, 1024, 132096>>>();
    final_kernel<<<BATCH, 1024>>>(out);
}